// round 16
// baseline (speedup 1.0000x reference)
#include <cuda_runtime.h>

#define H 256
#define H2 512
#define H3 768
#define NB 16
#define LC 128
#define LO 64
#define NOPT 5
#define EDIM 300
#define BO 80

static __device__ __align__(16) float g_zero[H];
static __device__ __align__(16) float g_xp_ctx_f[NB*LC*H3];
static __device__ __align__(16) float g_xp_ctx_b[NB*LC*H3];
static __device__ __align__(16) float g_out_ctx [NB*LC*H2];
static __device__ __align__(16) float g_ctx_key [NB*LC*H];
static __device__ __align__(16) float g_xp_opt_f[BO*LO*H3];
static __device__ __align__(16) float g_xp_opt_b[BO*LO*H3];
static __device__ __align__(16) float g_out_opt [BO*LO*H2];
static __device__ __align__(16) float g_opt_q   [BO*LO*H];
static __device__ __align__(16) float g_e       [BO*LO*LC];
static __device__ __align__(16) float g_alpha   [BO*LO*LC];
static __device__ __align__(16) float g_beta    [BO*LO*LC];
static __device__ __align__(16) float g_actx    [BO*LC*H];
static __device__ __align__(16) float g_aopt    [BO*LO*H];
static __device__ __align__(16) float g_xp_attc_f[BO*LC*H3];
static __device__ __align__(16) float g_xp_attc_b[BO*LC*H3];
static __device__ __align__(16) float g_xp_atto_f[BO*LO*H3];
static __device__ __align__(16) float g_xp_atto_b[BO*LO*H3];
static __device__ __align__(16) float g_out_attc[BO*LC*H2];
static __device__ __align__(16) float g_out_atto[BO*LO*H2];
static __device__ __align__(16) float g_mc[BO*H2];
static __device__ __align__(16) float g_mo[BO*H2];
static __device__ __align__(16) float g_logits[BO];

// ---------------- GEMM: Y[M,N] = X[M,K] @ W[N,K]^T + bias ----------------
#define BM 64
#define BN 64
#define BK 16
#define TS 68

__global__ __launch_bounds__(256) void gemm_bias(
    const float* __restrict__ X, const float* __restrict__ W,
    const float* __restrict__ bias, float* __restrict__ Y,
    int M, int N, int K)
{
    __shared__ float Xs[BK*TS];
    __shared__ float Ws[BK*TS];
    int bm = blockIdx.y*BM, bn = blockIdx.x*BN;
    int tid = threadIdx.x;
    int tr = tid >> 4, tc = tid & 15;
    float acc[4][4];
#pragma unroll
    for (int i=0;i<4;i++)
#pragma unroll
        for (int j=0;j<4;j++) acc[i][j]=0.f;

    for (int k0=0;k0<K;k0+=BK){
#pragma unroll
        for (int i=0;i<4;i++){
            int idx = tid + i*256;
            int m = idx >> 4, k = idx & 15;
            float xv = 0.f, wv = 0.f;
            if (k0+k < K){
                if (bm+m < M) xv = X[(size_t)(bm+m)*K + k0+k];
                if (bn+m < N) wv = W[(size_t)(bn+m)*K + k0+k];
            }
            Xs[k*TS+m] = xv;
            Ws[k*TS+m] = wv;
        }
        __syncthreads();
#pragma unroll
        for (int k=0;k<BK;k++){
            float4 x4 = *(const float4*)&Xs[k*TS + tr*4];
            float4 w4 = *(const float4*)&Ws[k*TS + tc*4];
            float xa[4] = {x4.x,x4.y,x4.z,x4.w};
            float wa[4] = {w4.x,w4.y,w4.z,w4.w};
#pragma unroll
            for (int i=0;i<4;i++)
#pragma unroll
                for (int j=0;j<4;j++) acc[i][j] += xa[i]*wa[j];
        }
        __syncthreads();
    }
#pragma unroll
    for (int i=0;i<4;i++){
        int m = bm + tr*4 + i;
        if (m >= M) continue;
#pragma unroll
        for (int j=0;j<4;j++){
            int n = bn + tc*4 + j;
            if (n >= N) continue;
            Y[(size_t)m*N + n] = acc[i][j] + (bias ? bias[n] : 0.f);
        }
    }
}

// ---------------- fused GRU step (4 independent jobs) ----------------
struct GruJob {
    const float* xp; const float* hprev; float* out;
    const float* Wh; const float* bh;
    long long xp_rs, hp_rs, out_rs; int nrows;
};
struct GruArgs { GruJob j[4]; };

__global__ __launch_bounds__(128) void gru_step(GruArgs a)
{
    GruJob jb = a.j[blockIdx.z];
    int r = blockIdx.y*16 + (threadIdx.x >> 3);
    if (r >= jb.nrows) return;
    int c = (blockIdx.x << 3) + (threadIdx.x & 7);

    const float4* hp = (const float4*)(jb.hprev + (long long)r * jb.hp_rs);
    const float4* wr = (const float4*)(jb.Wh + (long long)c * H);
    const float4* wz = (const float4*)(jb.Wh + (long long)(H + c) * H);
    const float4* wn = (const float4*)(jb.Wh + (long long)(2*H + c) * H);

    float ar=0.f, az=0.f, an=0.f;
#pragma unroll 4
    for (int k=0;k<H/4;k++){
        float4 h4 = __ldg(hp + k);
        float4 w4 = __ldg(wr + k);
        ar += h4.x*w4.x + h4.y*w4.y + h4.z*w4.z + h4.w*w4.w;
        w4 = __ldg(wz + k);
        az += h4.x*w4.x + h4.y*w4.y + h4.z*w4.z + h4.w*w4.w;
        w4 = __ldg(wn + k);
        an += h4.x*w4.x + h4.y*w4.y + h4.z*w4.z + h4.w*w4.w;
    }
    const float* xr = jb.xp + (long long)r * jb.xp_rs;
    float rg = 1.f / (1.f + expf(-(xr[c]     + ar + jb.bh[c])));
    float zg = 1.f / (1.f + expf(-(xr[H + c] + az + jb.bh[H + c])));
    float ng = tanhf(xr[2*H + c] + rg * (an + jb.bh[2*H + c]));
    float hold = jb.hprev[(long long)r * jb.hp_rs + c];
    jb.out[(long long)r * jb.out_rs + c] = (1.f - zg) * ng + zg * hold;
}

// ---------------- attention ----------------
__device__ __forceinline__ float tanh_ap(float x){
    float y; asm("tanh.approx.f32 %0, %1;" : "=f"(y) : "f"(x)); return y;
}

__global__ __launch_bounds__(256) void energies_k(
    const float* __restrict__ optq, const float* __restrict__ ctxk,
    const float* __restrict__ v, float* __restrict__ e)
{
    __shared__ float qs[16*129];
    __shared__ float cs[32*129];
    __shared__ float vs[128];
    int bo = blockIdx.x, b = bo / NOPT;
    int q0 = blockIdx.y * 16, c0 = blockIdx.z * 32;
    int tid = threadIdx.x;
    int tq = tid >> 4, tc2 = tid & 15;
    float acc0 = 0.f, acc1 = 0.f;

    for (int hc=0; hc<H; hc+=128){
        for (int i=tid; i<16*128; i+=256){
            int row = i >> 7, h = i & 127;
            qs[row*129 + h] = optq[((size_t)bo*LO + q0 + row)*H + hc + h];
        }
        for (int i=tid; i<32*128; i+=256){
            int row = i >> 7, h = i & 127;
            cs[row*129 + h] = ctxk[((size_t)b*LC + c0 + row)*H + hc + h];
        }
        if (tid < 128) vs[tid] = v[hc + tid];
        __syncthreads();
#pragma unroll 4
        for (int h=0; h<128; h++){
            float qv = qs[tq*129 + h];
            float vv = vs[h];
            acc0 += vv * tanh_ap(qv + cs[(tc2*2 + 0)*129 + h]);
            acc1 += vv * tanh_ap(qv + cs[(tc2*2 + 1)*129 + h]);
        }
        __syncthreads();
    }
    float* ep = e + ((size_t)bo*LO + q0 + tq)*LC + c0 + tc2*2;
    ep[0] = acc0; ep[1] = acc1;
}

__global__ __launch_bounds__(128) void softmax_q_k(
    const float* __restrict__ e, float* __restrict__ alpha)
{
    int bo = blockIdx.x, c = threadIdx.x;
    const float* ep = e + (size_t)bo*LO*LC + c;
    float m = -1e30f;
    for (int q=0;q<LO;q++) m = fmaxf(m, ep[q*LC]);
    float s = 0.f;
    for (int q=0;q<LO;q++) s += expf(ep[q*LC] - m);
    float inv = 1.f / s;
    float* ap = alpha + (size_t)bo*LO*LC + c;
    for (int q=0;q<LO;q++) ap[q*LC] = expf(ep[q*LC] - m) * inv;
}

__global__ __launch_bounds__(256) void agg_actx_k(
    const float* __restrict__ alpha, const float* __restrict__ optq,
    float* __restrict__ actx)
{
    int bo = blockIdx.x, c = blockIdx.y, h = threadIdx.x;
    const float* ap = alpha + (size_t)bo*LO*LC + c;
    const float* qp = optq + (size_t)bo*LO*H + h;
    float acc = 0.f;
    for (int q=0;q<LO;q++) acc += ap[q*LC] * qp[q*H];
    actx[((size_t)bo*LC + c)*H + h] = acc;
}

__global__ __launch_bounds__(128) void softmax_c_k(
    const float* __restrict__ e, float* __restrict__ beta)
{
    int row = blockIdx.x, c = threadIdx.x;
    float v = e[(size_t)row*LC + c];
    float m = v;
    for (int o=16;o>0;o>>=1) m = fmaxf(m, __shfl_xor_sync(0xffffffffu, m, o));
    __shared__ float sm[4], ss[4];
    if ((c & 31) == 0) sm[c>>5] = m;
    __syncthreads();
    m = fmaxf(fmaxf(sm[0],sm[1]), fmaxf(sm[2],sm[3]));
    float ex = expf(v - m);
    float s = ex;
    for (int o=16;o>0;o>>=1) s += __shfl_xor_sync(0xffffffffu, s, o);
    if ((c & 31) == 0) ss[c>>5] = s;
    __syncthreads();
    s = ss[0]+ss[1]+ss[2]+ss[3];
    beta[(size_t)row*LC + c] = ex / s;
}

__global__ __launch_bounds__(256) void agg_aopt_k(
    const float* __restrict__ beta, const float* __restrict__ ctxk,
    float* __restrict__ aopt)
{
    int bo = blockIdx.x, q = blockIdx.y, h = threadIdx.x;
    int b = bo / NOPT;
    const float* bp = beta + ((size_t)bo*LO + q)*LC;
    const float* kp = ctxk + (size_t)b*LC*H + h;
    float acc = 0.f;
    for (int c=0;c<LC;c++) acc += bp[c] * kp[c*H];
    aopt[((size_t)bo*LO + q)*H + h] = acc;
}

__global__ __launch_bounds__(512) void mean_k(
    const float* __restrict__ seq, float* __restrict__ out, int T)
{
    int bo = blockIdx.x, j = threadIdx.x;
    float s = 0.f;
    for (int t=0;t<T;t++) s += seq[((size_t)bo*T + t)*H2 + j];
    out[(size_t)bo*H2 + j] = s * (1.f / (float)T);
}

__global__ __launch_bounds__(128) void cosim_k(
    const float* __restrict__ mc, const float* __restrict__ mo,
    float* __restrict__ lg)
{
    int bo = blockIdx.x, tid = threadIdx.x;
    float d=0.f, na=0.f, nb=0.f;
    for (int j=tid;j<H2;j+=128){
        float a = mc[(size_t)bo*H2 + j], b = mo[(size_t)bo*H2 + j];
        d += a*b; na += a*a; nb += b*b;
    }
    __shared__ float sd[128], sa[128], sb[128];
    sd[tid]=d; sa[tid]=na; sb[tid]=nb;
    __syncthreads();
    for (int o=64;o>0;o>>=1){
        if (tid < o){ sd[tid]+=sd[tid+o]; sa[tid]+=sa[tid+o]; sb[tid]+=sb[tid+o]; }
        __syncthreads();
    }
    if (tid == 0){
        float va = fmaxf(sqrtf(sa[0]), 1e-8f);
        float vb = fmaxf(sqrtf(sb[0]), 1e-8f);
        lg[bo] = sd[0] / (va * vb);
    }
}

__global__ void final_k(const float* __restrict__ lg, float* __restrict__ out)
{
    int b = blockIdx.x, o = threadIdx.x;
    if (o >= NOPT) return;
    float m = -1e30f;
    for (int i=0;i<NOPT;i++) m = fmaxf(m, lg[b*NOPT + i]);
    float s = 0.f;
    for (int i=0;i<NOPT;i++) s += expf(lg[b*NOPT + i] - m);
    out[b*NOPT + o] = expf(lg[b*NOPT + o] - m) / s;
}

// ---------------- host ----------------
static void* sym(const void* s){ void* p=nullptr; cudaGetSymbolAddress(&p, s); return p; }

static void fill_job(GruJob& j, const float* xpB, float* outB,
                     const float* Wh, const float* bh, float* zero,
                     int t, int T, int rows, int bwd)
{
    int ti = bwd ? (T-1-t) : t;
    j.xp = xpB + (size_t)ti*H3;
    j.out = outB + (size_t)ti*H2 + (bwd ? H : 0);
    if (t == 0){ j.hprev = zero; j.hp_rs = 0; }
    else {
        int hpos = bwd ? (T-t) : (t-1);
        j.hprev = outB + (size_t)hpos*H2 + (bwd ? H : 0);
        j.hp_rs = (long long)T*H2;
    }
    j.Wh = Wh; j.bh = bh;
    j.xp_rs = (long long)T*H3;
    j.out_rs = (long long)T*H2;
    j.nrows = rows;
}

extern "C" void kernel_launch(void* const* d_in, const int* in_sizes, int n_in,
                              void* d_out, int out_size)
{
    const float* context = (const float*)d_in[0];
    const float* options = (const float*)d_in[2];
    const float* rWi_f=(const float*)d_in[4];  const float* rWh_f=(const float*)d_in[5];
    const float* rbi_f=(const float*)d_in[6];  const float* rbh_f=(const float*)d_in[7];
    const float* rWi_b=(const float*)d_in[8];  const float* rWh_b=(const float*)d_in[9];
    const float* rbi_b=(const float*)d_in[10]; const float* rbh_b=(const float*)d_in[11];
    const float* aWi_f=(const float*)d_in[12]; const float* aWh_f=(const float*)d_in[13];
    const float* abi_f=(const float*)d_in[14]; const float* abh_f=(const float*)d_in[15];
    const float* aWi_b=(const float*)d_in[16]; const float* aWh_b=(const float*)d_in[17];
    const float* abi_b=(const float*)d_in[18]; const float* abh_b=(const float*)d_in[19];
    const float* Wk=(const float*)d_in[20];    const float* Wq=(const float*)d_in[21];
    const float* venergy=(const float*)d_in[22];
    float* out = (float*)d_out;

    float* zero      = (float*)sym(g_zero);
    float* xp_ctx_f  = (float*)sym(g_xp_ctx_f);
    float* xp_ctx_b  = (float*)sym(g_xp_ctx_b);
    float* out_ctx   = (float*)sym(g_out_ctx);
    float* ctx_key   = (float*)sym(g_ctx_key);
    float* xp_opt_f  = (float*)sym(g_xp_opt_f);
    float* xp_opt_b  = (float*)sym(g_xp_opt_b);
    float* out_opt   = (float*)sym(g_out_opt);
    float* opt_q     = (float*)sym(g_opt_q);
    float* e         = (float*)sym(g_e);
    float* alpha     = (float*)sym(g_alpha);
    float* beta      = (float*)sym(g_beta);
    float* actx      = (float*)sym(g_actx);
    float* aopt      = (float*)sym(g_aopt);
    float* xp_attc_f = (float*)sym(g_xp_attc_f);
    float* xp_attc_b = (float*)sym(g_xp_attc_b);
    float* xp_atto_f = (float*)sym(g_xp_atto_f);
    float* xp_atto_b = (float*)sym(g_xp_atto_b);
    float* out_attc  = (float*)sym(g_out_attc);
    float* out_atto  = (float*)sym(g_out_atto);
    float* mc        = (float*)sym(g_mc);
    float* mo        = (float*)sym(g_mo);
    float* lg        = (float*)sym(g_logits);

    // encoder input projections
    gemm_bias<<<dim3(H3/BN, NB*LC/BM), 256>>>(context, rWi_f, rbi_f, xp_ctx_f, NB*LC, H3, EDIM);
    gemm_bias<<<dim3(H3/BN, NB*LC/BM), 256>>>(context, rWi_b, rbi_b, xp_ctx_b, NB*LC, H3, EDIM);
    gemm_bias<<<dim3(H3/BN, BO*LO/BM), 256>>>(options, rWi_f, rbi_f, xp_opt_f, BO*LO, H3, EDIM);
    gemm_bias<<<dim3(H3/BN, BO*LO/BM), 256>>>(options, rWi_b, rbi_b, xp_opt_b, BO*LO, H3, EDIM);

    // encoder GRU recurrence
    for (int t=0; t<LC; t++){
        int to = (t < LO) ? t : (LO-1);
        int on = (t < LO) ? BO : 0;
        GruArgs a;
        fill_job(a.j[0], xp_ctx_f, out_ctx, rWh_f, rbh_f, zero, t,  LC, NB, 0);
        fill_job(a.j[1], xp_ctx_b, out_ctx, rWh_b, rbh_b, zero, t,  LC, NB, 1);
        fill_job(a.j[2], xp_opt_f, out_opt, rWh_f, rbh_f, zero, to, LO, on, 0);
        fill_job(a.j[3], xp_opt_b, out_opt, rWh_b, rbh_b, zero, to, LO, on, 1);
        gru_step<<<dim3(H/8, BO/16, 4), 128>>>(a);
    }

    // key / query projections
    gemm_bias<<<dim3(H/BN, NB*LC/BM), 256>>>(out_ctx, Wk, nullptr, ctx_key, NB*LC, H, H2);
    gemm_bias<<<dim3(H/BN, BO*LO/BM), 256>>>(out_opt, Wq, nullptr, opt_q, BO*LO, H, H2);

    // attention
    energies_k<<<dim3(BO, LO/16, LC/32), 256>>>(opt_q, ctx_key, venergy, e);
    softmax_q_k<<<BO, 128>>>(e, alpha);
    agg_actx_k<<<dim3(BO, LC), 256>>>(alpha, opt_q, actx);
    softmax_c_k<<<BO*LO, 128>>>(e, beta);
    agg_aopt_k<<<dim3(BO, LO), 256>>>(beta, ctx_key, aopt);

    // attention-GRU input projections
    gemm_bias<<<dim3(H3/BN, BO*LC/BM), 256>>>(actx, aWi_f, abi_f, xp_attc_f, BO*LC, H3, H);
    gemm_bias<<<dim3(H3/BN, BO*LC/BM), 256>>>(actx, aWi_b, abi_b, xp_attc_b, BO*LC, H3, H);
    gemm_bias<<<dim3(H3/BN, BO*LO/BM), 256>>>(aopt, aWi_f, abi_f, xp_atto_f, BO*LO, H3, H);
    gemm_bias<<<dim3(H3/BN, BO*LO/BM), 256>>>(aopt, aWi_b, abi_b, xp_atto_b, BO*LO, H3, H);

    // attention GRU recurrence
    for (int t=0; t<LC; t++){
        int to = (t < LO) ? t : (LO-1);
        int on = (t < LO) ? BO : 0;
        GruArgs a;
        fill_job(a.j[0], xp_attc_f, out_attc, aWh_f, abh_f, zero, t,  LC, BO, 0);
        fill_job(a.j[1], xp_attc_b, out_attc, aWh_b, abh_b, zero, t,  LC, BO, 1);
        fill_job(a.j[2], xp_atto_f, out_atto, aWh_f, abh_f, zero, to, LO, on, 0);
        fill_job(a.j[3], xp_atto_b, out_atto, aWh_b, abh_b, zero, to, LO, on, 1);
        gru_step<<<dim3(H/8, BO/16, 4), 128>>>(a);
    }

    // means, cosine, final softmax
    mean_k<<<BO, 512>>>(out_attc, mc, LC);
    mean_k<<<BO, 512>>>(out_atto, mo, LO);
    cosim_k<<<BO, 128>>>(mc, mo, lg);
    final_k<<<NB, 8>>>(lg, out);
}

// round 17
// speedup vs baseline: 1.1847x; 1.1847x over previous
#include <cuda_runtime.h>

#define H 256
#define H2 512
#define H3 768
#define NB 16
#define LC 128
#define LO 64
#define NOPT 5
#define EDIM 300
#define BO 80

static __device__ __align__(16) float g_zero[H];
static __device__ __align__(16) float g_xp_ctx_f[NB*LC*H3];
static __device__ __align__(16) float g_xp_ctx_b[NB*LC*H3];
static __device__ __align__(16) float g_out_ctx [NB*LC*H2];
static __device__ __align__(16) float g_ctx_key [NB*LC*H];
static __device__ __align__(16) float g_xp_opt_f[BO*LO*H3];
static __device__ __align__(16) float g_xp_opt_b[BO*LO*H3];
static __device__ __align__(16) float g_out_opt [BO*LO*H2];
static __device__ __align__(16) float g_opt_q   [BO*LO*H];
static __device__ __align__(16) float g_e       [BO*LO*LC];
static __device__ __align__(16) float g_alpha   [BO*LO*LC];
static __device__ __align__(16) float g_beta    [BO*LO*LC];
static __device__ __align__(16) float g_actx    [BO*LC*H];
static __device__ __align__(16) float g_aopt    [BO*LO*H];
static __device__ __align__(16) float g_xp_attc_f[BO*LC*H3];
static __device__ __align__(16) float g_xp_attc_b[BO*LC*H3];
static __device__ __align__(16) float g_xp_atto_f[BO*LO*H3];
static __device__ __align__(16) float g_xp_atto_b[BO*LO*H3];
static __device__ __align__(16) float g_out_attc[BO*LC*H2];
static __device__ __align__(16) float g_out_atto[BO*LO*H2];
static __device__ __align__(16) float g_mc[BO*H2];
static __device__ __align__(16) float g_mo[BO*H2];
static __device__ __align__(16) float g_logits[BO];

// grid-barrier state: 0/0 at entry; each chain runs an EVEN number of
// barriers so the sense flag returns to 0 for the next launch / replay.
static __device__ int          g_bar_count;
static __device__ volatile int g_bar_flag;

// ---------------- GEMM: Y[M,N] = X[M,K] @ W[N,K]^T + bias ----------------
#define BM 64
#define BN 64
#define BK 16
#define TS 68

__global__ __launch_bounds__(256) void gemm_bias(
    const float* __restrict__ X, const float* __restrict__ W,
    const float* __restrict__ bias, float* __restrict__ Y,
    int M, int N, int K)
{
    __shared__ float Xs[BK*TS];
    __shared__ float Ws[BK*TS];
    int bm = blockIdx.y*BM, bn = blockIdx.x*BN;
    int tid = threadIdx.x;
    int tr = tid >> 4, tc = tid & 15;
    float acc[4][4];
#pragma unroll
    for (int i=0;i<4;i++)
#pragma unroll
        for (int j=0;j<4;j++) acc[i][j]=0.f;

    for (int k0=0;k0<K;k0+=BK){
#pragma unroll
        for (int i=0;i<4;i++){
            int idx = tid + i*256;
            int m = idx >> 4, k = idx & 15;
            float xv = 0.f, wv = 0.f;
            if (k0+k < K){
                if (bm+m < M) xv = X[(size_t)(bm+m)*K + k0+k];
                if (bn+m < N) wv = W[(size_t)(bn+m)*K + k0+k];
            }
            Xs[k*TS+m] = xv;
            Ws[k*TS+m] = wv;
        }
        __syncthreads();
#pragma unroll
        for (int k=0;k<BK;k++){
            float4 x4 = *(const float4*)&Xs[k*TS + tr*4];
            float4 w4 = *(const float4*)&Ws[k*TS + tc*4];
            float xa[4] = {x4.x,x4.y,x4.z,x4.w};
            float wa[4] = {w4.x,w4.y,w4.z,w4.w};
#pragma unroll
            for (int i=0;i<4;i++)
#pragma unroll
                for (int j=0;j<4;j++) acc[i][j] += xa[i]*wa[j];
        }
        __syncthreads();
    }
#pragma unroll
    for (int i=0;i<4;i++){
        int m = bm + tr*4 + i;
        if (m >= M) continue;
#pragma unroll
        for (int j=0;j<4;j++){
            int n = bn + tc*4 + j;
            if (n >= N) continue;
            Y[(size_t)m*N + n] = acc[i][j] + (bias ? bias[n] : 0.f);
        }
    }
}

// ---------------- persistent GRU chain ----------------
struct ChainJob {
    const float* xp;   // [(r*T + t)*H3]
    float* outb;       // [(r*T + t)*H2 + off + c]
    const float* Wh;   // [3H,H]
    const float* bh;   // [3H]
    int T; int rows; int bwd; int off;
};
struct ChainArgs { ChainJob j[4]; int pre[5]; };

__device__ __forceinline__ void grid_bar(int nblocks, int sense)
{
    __threadfence();
    __syncthreads();
    if (threadIdx.x == 0){
        int old = atomicAdd(&g_bar_count, 1);
        if (old == nblocks - 1){
            g_bar_count = 0;
            __threadfence();
            g_bar_flag = sense;
        } else {
            while (g_bar_flag != sense) { }
        }
    }
    __syncthreads();
}

__global__ __launch_bounds__(128, 6) void gru_chain(
    ChainArgs a, const float* __restrict__ zero, int steps, int nblocks)
{
    int colg = blockIdx.x & 31;
    int grp  = blockIdx.x >> 5;
    int ji = 0;
    while (grp >= a.pre[ji+1]) ji++;
    ChainJob jb = a.j[ji];
    int rg = grp - a.pre[ji];
    int r = rg*16 + (threadIdx.x >> 3);
    int c = colg*8 + (threadIdx.x & 7);
    bool act = (r < jb.rows);

    const float4* wr = (const float4*)(jb.Wh + (size_t)c * H);
    const float4* wz = (const float4*)(jb.Wh + (size_t)(H + c) * H);
    const float4* wn = (const float4*)(jb.Wh + (size_t)(2*H + c) * H);
    float bhr = jb.bh[c], bhz = jb.bh[H + c], bhn = jb.bh[2*H + c];

    for (int t = 0; t < steps; t++){
        if (act && t < jb.T){
            int ti = jb.bwd ? (jb.T - 1 - t) : t;
            const float* hrow;
            if (t == 0) hrow = zero;
            else {
                int tp = jb.bwd ? (ti + 1) : (ti - 1);
                hrow = jb.outb + ((size_t)r * jb.T + tp) * H2 + jb.off;
            }
            const float4* hp = (const float4*)hrow;
            float ar=0.f, az=0.f, an=0.f;
#pragma unroll 4
            for (int k=0;k<H/4;k++){
                float4 h4 = __ldg(hp + k);
                float4 w4 = __ldg(wr + k);
                ar += h4.x*w4.x + h4.y*w4.y + h4.z*w4.z + h4.w*w4.w;
                w4 = __ldg(wz + k);
                az += h4.x*w4.x + h4.y*w4.y + h4.z*w4.z + h4.w*w4.w;
                w4 = __ldg(wn + k);
                an += h4.x*w4.x + h4.y*w4.y + h4.z*w4.z + h4.w*w4.w;
            }
            const float* xr = jb.xp + ((size_t)r * jb.T + ti) * H3;
            float rgg = 1.f / (1.f + expf(-(xr[c]       + ar + bhr)));
            float zg  = 1.f / (1.f + expf(-(xr[H + c]   + az + bhz)));
            float ng  = tanhf(xr[2*H + c] + rgg * (an + bhn));
            float hold = hrow[c];
            jb.outb[((size_t)r * jb.T + ti) * H2 + jb.off + c] =
                (1.f - zg) * ng + zg * hold;
        }
        grid_bar(nblocks, (t & 1) ^ 1);
    }
}

// ---------------- attention ----------------
__device__ __forceinline__ float tanh_ap(float x){
    float y; asm("tanh.approx.f32 %0, %1;" : "=f"(y) : "f"(x)); return y;
}

__global__ __launch_bounds__(256) void energies_k(
    const float* __restrict__ optq, const float* __restrict__ ctxk,
    const float* __restrict__ v, float* __restrict__ e)
{
    __shared__ float qs[16*129];
    __shared__ float cs[32*129];
    __shared__ float vs[128];
    int bo = blockIdx.x, b = bo / NOPT;
    int q0 = blockIdx.y * 16, c0 = blockIdx.z * 32;
    int tid = threadIdx.x;
    int tq = tid >> 4, tc2 = tid & 15;
    float acc0 = 0.f, acc1 = 0.f;

    for (int hc=0; hc<H; hc+=128){
        for (int i=tid; i<16*128; i+=256){
            int row = i >> 7, h = i & 127;
            qs[row*129 + h] = optq[((size_t)bo*LO + q0 + row)*H + hc + h];
        }
        for (int i=tid; i<32*128; i+=256){
            int row = i >> 7, h = i & 127;
            cs[row*129 + h] = ctxk[((size_t)b*LC + c0 + row)*H + hc + h];
        }
        if (tid < 128) vs[tid] = v[hc + tid];
        __syncthreads();
#pragma unroll 4
        for (int h=0; h<128; h++){
            float qv = qs[tq*129 + h];
            float vv = vs[h];
            acc0 += vv * tanh_ap(qv + cs[(tc2*2 + 0)*129 + h]);
            acc1 += vv * tanh_ap(qv + cs[(tc2*2 + 1)*129 + h]);
        }
        __syncthreads();
    }
    float* ep = e + ((size_t)bo*LO + q0 + tq)*LC + c0 + tc2*2;
    ep[0] = acc0; ep[1] = acc1;
}

__global__ __launch_bounds__(128) void softmax_q_k(
    const float* __restrict__ e, float* __restrict__ alpha)
{
    int bo = blockIdx.x, c = threadIdx.x;
    const float* ep = e + (size_t)bo*LO*LC + c;
    float m = -1e30f;
    for (int q=0;q<LO;q++) m = fmaxf(m, ep[q*LC]);
    float s = 0.f;
    for (int q=0;q<LO;q++) s += expf(ep[q*LC] - m);
    float inv = 1.f / s;
    float* ap = alpha + (size_t)bo*LO*LC + c;
    for (int q=0;q<LO;q++) ap[q*LC] = expf(ep[q*LC] - m) * inv;
}

__global__ __launch_bounds__(256) void agg_actx_k(
    const float* __restrict__ alpha, const float* __restrict__ optq,
    float* __restrict__ actx)
{
    int bo = blockIdx.x, c = blockIdx.y, h = threadIdx.x;
    const float* ap = alpha + (size_t)bo*LO*LC + c;
    const float* qp = optq + (size_t)bo*LO*H + h;
    float acc = 0.f;
    for (int q=0;q<LO;q++) acc += ap[q*LC] * qp[q*H];
    actx[((size_t)bo*LC + c)*H + h] = acc;
}

__global__ __launch_bounds__(128) void softmax_c_k(
    const float* __restrict__ e, float* __restrict__ beta)
{
    int row = blockIdx.x, c = threadIdx.x;
    float v = e[(size_t)row*LC + c];
    float m = v;
    for (int o=16;o>0;o>>=1) m = fmaxf(m, __shfl_xor_sync(0xffffffffu, m, o));
    __shared__ float sm[4], ss[4];
    if ((c & 31) == 0) sm[c>>5] = m;
    __syncthreads();
    m = fmaxf(fmaxf(sm[0],sm[1]), fmaxf(sm[2],sm[3]));
    float ex = expf(v - m);
    float s = ex;
    for (int o=16;o>0;o>>=1) s += __shfl_xor_sync(0xffffffffu, s, o);
    if ((c & 31) == 0) ss[c>>5] = s;
    __syncthreads();
    s = ss[0]+ss[1]+ss[2]+ss[3];
    beta[(size_t)row*LC + c] = ex / s;
}

__global__ __launch_bounds__(256) void agg_aopt_k(
    const float* __restrict__ beta, const float* __restrict__ ctxk,
    float* __restrict__ aopt)
{
    int bo = blockIdx.x, q = blockIdx.y, h = threadIdx.x;
    int b = bo / NOPT;
    const float* bp = beta + ((size_t)bo*LO + q)*LC;
    const float* kp = ctxk + (size_t)b*LC*H + h;
    float acc = 0.f;
    for (int c=0;c<LC;c++) acc += bp[c] * kp[c*H];
    aopt[((size_t)bo*LO + q)*H + h] = acc;
}

__global__ __launch_bounds__(512) void mean_k(
    const float* __restrict__ seq, float* __restrict__ out, int T)
{
    int bo = blockIdx.x, j = threadIdx.x;
    float s = 0.f;
    for (int t=0;t<T;t++) s += seq[((size_t)bo*T + t)*H2 + j];
    out[(size_t)bo*H2 + j] = s * (1.f / (float)T);
}

__global__ __launch_bounds__(128) void cosim_k(
    const float* __restrict__ mc, const float* __restrict__ mo,
    float* __restrict__ lg)
{
    int bo = blockIdx.x, tid = threadIdx.x;
    float d=0.f, na=0.f, nb=0.f;
    for (int j=tid;j<H2;j+=128){
        float a = mc[(size_t)bo*H2 + j], b = mo[(size_t)bo*H2 + j];
        d += a*b; na += a*a; nb += b*b;
    }
    __shared__ float sd[128], sa[128], sb[128];
    sd[tid]=d; sa[tid]=na; sb[tid]=nb;
    __syncthreads();
    for (int o=64;o>0;o>>=1){
        if (tid < o){ sd[tid]+=sd[tid+o]; sa[tid]+=sa[tid+o]; sb[tid]+=sb[tid+o]; }
        __syncthreads();
    }
    if (tid == 0){
        float va = fmaxf(sqrtf(sa[0]), 1e-8f);
        float vb = fmaxf(sqrtf(sb[0]), 1e-8f);
        lg[bo] = sd[0] / (va * vb);
    }
}

__global__ void final_k(const float* __restrict__ lg, float* __restrict__ out)
{
    int b = blockIdx.x, o = threadIdx.x;
    if (o >= NOPT) return;
    float m = -1e30f;
    for (int i=0;i<NOPT;i++) m = fmaxf(m, lg[b*NOPT + i]);
    float s = 0.f;
    for (int i=0;i<NOPT;i++) s += expf(lg[b*NOPT + i] - m);
    out[b*NOPT + o] = expf(lg[b*NOPT + o] - m) / s;
}

// ---------------- host ----------------
static void* sym(const void* s){ void* p=nullptr; cudaGetSymbolAddress(&p, s); return p; }

static void set_job(ChainJob& j, const float* xp, float* outb,
                    const float* Wh, const float* bh,
                    int T, int rows, int bwd, int off)
{
    j.xp = xp; j.outb = outb; j.Wh = Wh; j.bh = bh;
    j.T = T; j.rows = rows; j.bwd = bwd; j.off = off;
}

extern "C" void kernel_launch(void* const* d_in, const int* in_sizes, int n_in,
                              void* d_out, int out_size)
{
    const float* context = (const float*)d_in[0];
    const float* options = (const float*)d_in[2];
    const float* rWi_f=(const float*)d_in[4];  const float* rWh_f=(const float*)d_in[5];
    const float* rbi_f=(const float*)d_in[6];  const float* rbh_f=(const float*)d_in[7];
    const float* rWi_b=(const float*)d_in[8];  const float* rWh_b=(const float*)d_in[9];
    const float* rbi_b=(const float*)d_in[10]; const float* rbh_b=(const float*)d_in[11];
    const float* aWi_f=(const float*)d_in[12]; const float* aWh_f=(const float*)d_in[13];
    const float* abi_f=(const float*)d_in[14]; const float* abh_f=(const float*)d_in[15];
    const float* aWi_b=(const float*)d_in[16]; const float* aWh_b=(const float*)d_in[17];
    const float* abi_b=(const float*)d_in[18]; const float* abh_b=(const float*)d_in[19];
    const float* Wk=(const float*)d_in[20];    const float* Wq=(const float*)d_in[21];
    const float* venergy=(const float*)d_in[22];
    float* out = (float*)d_out;

    float* zero      = (float*)sym(g_zero);
    float* xp_ctx_f  = (float*)sym(g_xp_ctx_f);
    float* xp_ctx_b  = (float*)sym(g_xp_ctx_b);
    float* out_ctx   = (float*)sym(g_out_ctx);
    float* ctx_key   = (float*)sym(g_ctx_key);
    float* xp_opt_f  = (float*)sym(g_xp_opt_f);
    float* xp_opt_b  = (float*)sym(g_xp_opt_b);
    float* out_opt   = (float*)sym(g_out_opt);
    float* opt_q     = (float*)sym(g_opt_q);
    float* e         = (float*)sym(g_e);
    float* alpha     = (float*)sym(g_alpha);
    float* beta      = (float*)sym(g_beta);
    float* actx      = (float*)sym(g_actx);
    float* aopt      = (float*)sym(g_aopt);
    float* xp_attc_f = (float*)sym(g_xp_attc_f);
    float* xp_attc_b = (float*)sym(g_xp_attc_b);
    float* xp_atto_f = (float*)sym(g_xp_atto_f);
    float* xp_atto_b = (float*)sym(g_xp_atto_b);
    float* out_attc  = (float*)sym(g_out_attc);
    float* out_atto  = (float*)sym(g_out_atto);
    float* mc        = (float*)sym(g_mc);
    float* mo        = (float*)sym(g_mo);
    float* lg        = (float*)sym(g_logits);

    // encoder input projections
    gemm_bias<<<dim3(H3/BN, NB*LC/BM), 256>>>(context, rWi_f, rbi_f, xp_ctx_f, NB*LC, H3, EDIM);
    gemm_bias<<<dim3(H3/BN, NB*LC/BM), 256>>>(context, rWi_b, rbi_b, xp_ctx_b, NB*LC, H3, EDIM);
    gemm_bias<<<dim3(H3/BN, BO*LO/BM), 256>>>(options, rWi_f, rbi_f, xp_opt_f, BO*LO, H3, EDIM);
    gemm_bias<<<dim3(H3/BN, BO*LO/BM), 256>>>(options, rWi_b, rbi_b, xp_opt_b, BO*LO, H3, EDIM);

    // encoder GRU chain (one persistent launch, 128 steps)
    {
        ChainArgs a;
        set_job(a.j[0], xp_ctx_f, out_ctx, rWh_f, rbh_f, LC, NB, 0, 0);
        set_job(a.j[1], xp_ctx_b, out_ctx, rWh_b, rbh_b, LC, NB, 1, H);
        set_job(a.j[2], xp_opt_f, out_opt, rWh_f, rbh_f, LO, BO, 0, 0);
        set_job(a.j[3], xp_opt_b, out_opt, rWh_b, rbh_b, LO, BO, 1, H);
        a.pre[0]=0; a.pre[1]=1; a.pre[2]=2; a.pre[3]=7; a.pre[4]=12;
        int nblocks = 12*32;
        gru_chain<<<nblocks, 128>>>(a, zero, LC, nblocks);
    }

    // key / query projections
    gemm_bias<<<dim3(H/BN, NB*LC/BM), 256>>>(out_ctx, Wk, nullptr, ctx_key, NB*LC, H, H2);
    gemm_bias<<<dim3(H/BN, BO*LO/BM), 256>>>(out_opt, Wq, nullptr, opt_q, BO*LO, H, H2);

    // attention
    energies_k<<<dim3(BO, LO/16, LC/32), 256>>>(opt_q, ctx_key, venergy, e);
    softmax_q_k<<<BO, 128>>>(e, alpha);
    agg_actx_k<<<dim3(BO, LC), 256>>>(alpha, opt_q, actx);
    softmax_c_k<<<BO*LO, 128>>>(e, beta);
    agg_aopt_k<<<dim3(BO, LO), 256>>>(beta, ctx_key, aopt);

    // attention-GRU input projections
    gemm_bias<<<dim3(H3/BN, BO*LC/BM), 256>>>(actx, aWi_f, abi_f, xp_attc_f, BO*LC, H3, H);
    gemm_bias<<<dim3(H3/BN, BO*LC/BM), 256>>>(actx, aWi_b, abi_b, xp_attc_b, BO*LC, H3, H);
    gemm_bias<<<dim3(H3/BN, BO*LO/BM), 256>>>(aopt, aWi_f, abi_f, xp_atto_f, BO*LO, H3, H);
    gemm_bias<<<dim3(H3/BN, BO*LO/BM), 256>>>(aopt, aWi_b, abi_b, xp_atto_b, BO*LO, H3, H);

    // attention GRU chain
    {
        ChainArgs a;
        set_job(a.j[0], xp_attc_f, out_attc, aWh_f, abh_f, LC, BO, 0, 0);
        set_job(a.j[1], xp_attc_b, out_attc, aWh_b, abh_b, LC, BO, 1, H);
        set_job(a.j[2], xp_atto_f, out_atto, aWh_f, abh_f, LO, BO, 0, 0);
        set_job(a.j[3], xp_atto_b, out_atto, aWh_b, abh_b, LO, BO, 1, H);
        a.pre[0]=0; a.pre[1]=5; a.pre[2]=10; a.pre[3]=15; a.pre[4]=20;
        int nblocks = 20*32;
        gru_chain<<<nblocks, 128>>>(a, zero, LC, nblocks);
    }

    // means, cosine, final softmax
    mean_k<<<BO, 512>>>(out_attc, mc, LC);
    mean_k<<<BO, 512>>>(out_atto, mo, LO);
    cosim_k<<<BO, 128>>>(mc, mo, lg);
    final_k<<<NB, 8>>>(lg, out);
}